// round 5
// baseline (speedup 1.0000x reference)
#include <cuda_runtime.h>
#include <cuda_fp16.h>
#include <math.h>
#include <stdint.h>

#define T_TOK 1024
#define HID   2048
#define NEXP  16
#define TOPK  4
#define IEXP  1408
#define ISH   2816

// ---------------- scratch (__device__ globals) ----------------
__device__ __align__(1024) __half g_w1h[(size_t)NEXP * 2 * IEXP * HID];
__device__ __align__(1024) __half g_w2h[(size_t)NEXP * HID * IEXP];
__device__ __align__(1024) __half g_wsgh[(size_t)2 * ISH * HID];
__device__ __align__(1024) __half g_wsdh[(size_t)HID * ISH];
__device__ __align__(1024) __half g_xh[(size_t)T_TOK * HID];
__device__ __align__(1024) __half g_xg[(size_t)NEXP * T_TOK * HID];
__device__ __align__(1024) __half g_acth[(size_t)NEXP * T_TOK * IEXP];
__device__ __align__(1024) __half g_ashh[(size_t)T_TOK * ISH];
__device__ float g_ysc[(size_t)NEXP * T_TOK * HID];
__device__ float g_sout[(size_t)T_TOK * HID];
__device__ int   g_cnt[NEXP];
__device__ int   g_te[T_TOK * TOPK];
__device__ int   g_slot[T_TOK * TOPK];
__device__ float g_tw[T_TOK * TOPK];

// ---------------- PTX helpers (plain sm_80-era PTX only) ----------------
__device__ __forceinline__ uint32_t smem_u32(const void* p) {
    uint32_t a;
    asm("{ .reg .u64 t; cvta.to.shared.u64 t, %1; cvt.u32.u64 %0, t; }" : "=r"(a) : "l"(p));
    return a;
}
#define CP16(dst, src) asm volatile("cp.async.cg.shared.global [%0], [%1], 16;" :: "r"(dst), "l"(src) : "memory")
#define CPCOMMIT()     asm volatile("cp.async.commit_group;" ::: "memory")
#define CPWAIT(n)      asm volatile("cp.async.wait_group %0;" :: "n"(n) : "memory")

__device__ __forceinline__ void ldsm4(uint32_t addr, uint32_t& r0, uint32_t& r1,
                                      uint32_t& r2, uint32_t& r3) {
    asm volatile("ldmatrix.sync.aligned.m8n8.x4.shared.b16 {%0,%1,%2,%3}, [%4];"
                 : "=r"(r0), "=r"(r1), "=r"(r2), "=r"(r3) : "r"(addr));
}
__device__ __forceinline__ void mma16816(float* c, uint32_t a0, uint32_t a1, uint32_t a2,
                                         uint32_t a3, uint32_t b0, uint32_t b1) {
    asm volatile(
        "mma.sync.aligned.m16n8k16.row.col.f32.f16.f16.f32 "
        "{%0,%1,%2,%3}, {%4,%5,%6,%7}, {%8,%9}, {%0,%1,%2,%3};"
        : "+f"(c[0]), "+f"(c[1]), "+f"(c[2]), "+f"(c[3])
        : "r"(a0), "r"(a1), "r"(a2), "r"(a3), "r"(b0), "r"(b1));
}

#define SWZ(o) ((o) ^ (((o) >> 3) & 0x70))
#define NSTAGE 3
#define STAGE_B 32768
#define SMEM_DYN (NSTAGE * STAGE_B + 1024)

// ---------------- fp32 -> fp16 conversion ----------------
__global__ void conv_kernel(const float* __restrict__ src, __half* __restrict__ dst) {
    size_t i = ((size_t)blockIdx.x * 256 + threadIdx.x) * 8;
    float4 a = *(const float4*)(src + i);
    float4 b = *(const float4*)(src + i + 4);
    __half2 h0 = __floats2half2_rn(a.x, a.y), h1 = __floats2half2_rn(a.z, a.w);
    __half2 h2 = __floats2half2_rn(b.x, b.y), h3 = __floats2half2_rn(b.z, b.w);
    uint4 o;
    o.x = *(uint32_t*)&h0; o.y = *(uint32_t*)&h1; o.z = *(uint32_t*)&h2; o.w = *(uint32_t*)&h3;
    *(uint4*)(dst + i) = o;
}

__global__ void zero_kernel() { if (threadIdx.x < NEXP) g_cnt[threadIdx.x] = 0; }

// ---------------- router (fp32, unchanged) ----------------
__global__ void router_kernel(const float* __restrict__ x, const float* __restrict__ Wg) {
    int t = blockIdx.x;
    const float* xr = x + (size_t)t * HID;
    float acc[NEXP];
#pragma unroll
    for (int e = 0; e < NEXP; e++) acc[e] = 0.f;
    for (int h = threadIdx.x; h < HID; h += 128) {
        float xv = xr[h];
        const float* wr = Wg + (size_t)h * NEXP;
#pragma unroll
        for (int e = 0; e < NEXP; e++) acc[e] = fmaf(xv, wr[e], acc[e]);
    }
    __shared__ float red[128 * NEXP];
#pragma unroll
    for (int e = 0; e < NEXP; e++) red[threadIdx.x * NEXP + e] = acc[e];
    __syncthreads();
    __shared__ float logits[NEXP];
    if (threadIdx.x < NEXP) {
        float s = 0.f;
        for (int i = 0; i < 128; i++) s += red[i * NEXP + threadIdx.x];
        logits[threadIdx.x] = s;
    }
    __syncthreads();
    if (threadIdx.x == 0) {
        float lv[NEXP];
#pragma unroll
        for (int e = 0; e < NEXP; e++) lv[e] = logits[e];
        int ids[TOPK]; float vals[TOPK];
        bool used[NEXP];
#pragma unroll
        for (int e = 0; e < NEXP; e++) used[e] = false;
        for (int k = 0; k < TOPK; k++) {
            int bi = 0; float bv = -3.4e38f;
            for (int e = 0; e < NEXP; e++)
                if (!used[e] && lv[e] > bv) { bv = lv[e]; bi = e; }
            used[bi] = true; ids[k] = bi; vals[k] = bv;
        }
        float m = vals[0], ssum = 0.f, wv[TOPK];
        for (int k = 0; k < TOPK; k++) { wv[k] = expf(vals[k] - m); ssum += wv[k]; }
        float inv = 1.f / ssum;
        for (int k = 0; k < TOPK; k++) {
            int e = ids[k];
            int slot = atomicAdd(&g_cnt[e], 1);
            g_te[t * TOPK + k]   = e;
            g_slot[t * TOPK + k] = slot;
            g_tw[t * TOPK + k]   = wv[k] * inv;
        }
    }
}

// ---------------- gather x rows (fp16) into per-expert contiguous buffers ----------------
__global__ void gather_kernel() {
    int b = blockIdx.x;
    int t = b >> 2, k = b & 3;
    int e = g_te[t * TOPK + k], slot = g_slot[t * TOPK + k];
    const uint4* src = (const uint4*)(g_xh + (size_t)t * HID);
    uint4* dst = (uint4*)(g_xg + ((size_t)e * T_TOK + slot) * HID);
    dst[threadIdx.x] = src[threadIdx.x];
}

// ---------------- gemm1 (mma.sync): C[128rows, 64 gate + 64 up] -> silu*mul -> fp16 act ----------------
__global__ void __launch_bounds__(256) gemm1_mma(int shared_mode) {
    int e = blockIdx.z;
    const __half* A; const __half* B; __half* act;
    int nrows, Ihalf;
    const int K = HID;
    if (shared_mode) { A = g_xh; B = g_wsgh; act = g_ashh; nrows = T_TOK; Ihalf = ISH; }
    else {
        A = g_xg + (size_t)e * T_TOK * HID;
        B = g_w1h + (size_t)e * 2 * IEXP * HID;
        act = g_acth + (size_t)e * T_TOK * IEXP;
        nrows = g_cnt[e]; Ihalf = IEXP;
    }
    int m0 = blockIdx.y * 128;
    if (m0 >= nrows) return;
    int j0 = blockIdx.x * 64;

    extern __shared__ char smraw[];
    uint32_t sb = (smem_u32(smraw) + 1023) & ~1023u;
    int tid = threadIdx.x, lane = tid & 31, wid = tid >> 5;
    int wm = wid & 3, wn = wid >> 2;

    const __half* asrc[4]; const __half* bsrc[4]; uint32_t swz[4];
#pragma unroll
    for (int i = 0; i < 4; i++) {
        int row = (tid >> 3) + 32 * i;
        int c16 = tid & 7;
        asrc[i] = A + (size_t)(m0 + row) * K + c16 * 8;
        int brow = (row < 64) ? (j0 + row) : (Ihalf + j0 + row - 64);
        bsrc[i] = B + (size_t)brow * K + c16 * 8;
        swz[i] = SWZ((uint32_t)(row * 128 + c16 * 16));
    }

    const int KT = K / 64;
    for (int s = 0; s < NSTAGE - 1; s++) {
        uint32_t sA = sb + s * STAGE_B, sB = sA + 16384;
        int ko = s * 64;
#pragma unroll
        for (int i = 0; i < 4; i++) { CP16(sA + swz[i], asrc[i] + ko); CP16(sB + swz[i], bsrc[i] + ko); }
        CPCOMMIT();
    }

    float ct[2][8][4];
#pragma unroll
    for (int mi = 0; mi < 2; mi++)
#pragma unroll
        for (int j = 0; j < 8; j++)
#pragma unroll
            for (int q = 0; q < 4; q++) ct[mi][j][q] = 0.f;

    uint32_t l15 = (uint32_t)(lane & 15);
    uint32_t kcb = ((lane >> 4) << 4);

    for (int kt = 0; kt < KT; kt++) {
        CPWAIT(1);
        __syncthreads();
        uint32_t sA = sb + (kt % NSTAGE) * STAGE_B, sB = sA + 16384;
#pragma unroll
        for (int ks = 0; ks < 4; ks++) {
            uint32_t a0[4], a1[4];
            ldsm4(sA + SWZ((uint32_t)((wm * 32 + l15) * 128) + ks * 32 + kcb), a0[0], a0[1], a0[2], a0[3]);
            ldsm4(sA + SWZ((uint32_t)((wm * 32 + 16 + l15) * 128) + ks * 32 + kcb), a1[0], a1[1], a1[2], a1[3]);
#pragma unroll
            for (int bb = 0; bb < 2; bb++) {
                uint32_t b0, b1, b2, b3;
                ldsm4(sB + SWZ((uint32_t)((wn * 32 + bb * 16 + l15) * 128) + ks * 32 + kcb), b0, b1, b2, b3);
                mma16816(ct[0][2 * bb],     a0[0], a0[1], a0[2], a0[3], b0, b2);
                mma16816(ct[0][2 * bb + 1], a0[0], a0[1], a0[2], a0[3], b1, b3);
                mma16816(ct[1][2 * bb],     a1[0], a1[1], a1[2], a1[3], b0, b2);
                mma16816(ct[1][2 * bb + 1], a1[0], a1[1], a1[2], a1[3], b1, b3);
            }
#pragma unroll
            for (int bb = 0; bb < 2; bb++) {
                uint32_t b0, b1, b2, b3;
                ldsm4(sB + SWZ((uint32_t)((64 + wn * 32 + bb * 16 + l15) * 128) + ks * 32 + kcb), b0, b1, b2, b3);
                mma16816(ct[0][4 + 2 * bb],     a0[0], a0[1], a0[2], a0[3], b0, b2);
                mma16816(ct[0][4 + 2 * bb + 1], a0[0], a0[1], a0[2], a0[3], b1, b3);
                mma16816(ct[1][4 + 2 * bb],     a1[0], a1[1], a1[2], a1[3], b0, b2);
                mma16816(ct[1][4 + 2 * bb + 1], a1[0], a1[1], a1[2], a1[3], b1, b3);
            }
        }
        __syncthreads();
        int nc = kt + NSTAGE - 1;
        if (nc < KT) {
            uint32_t dA = sb + (nc % NSTAGE) * STAGE_B, dB = dA + 16384;
            int ko = nc * 64;
#pragma unroll
            for (int i = 0; i < 4; i++) { CP16(dA + swz[i], asrc[i] + ko); CP16(dB + swz[i], bsrc[i] + ko); }
        }
        CPCOMMIT();
    }

#pragma unroll
    for (int mi = 0; mi < 2; mi++) {
        int row = m0 + wm * 32 + mi * 16 + (lane >> 2);
#pragma unroll
        for (int ni = 0; ni < 4; ni++) {
            int col = j0 + wn * 32 + ni * 8 + (lane & 3) * 2;
            if (row < nrows) {
                float g0 = ct[mi][ni][0], g1 = ct[mi][ni][1];
                float u0 = ct[mi][ni + 4][0], u1 = ct[mi][ni + 4][1];
                __half2 h = __floats2half2_rn(g0 / (1.f + expf(-g0)) * u0,
                                              g1 / (1.f + expf(-g1)) * u1);
                *(__half2*)(act + (size_t)row * Ihalf + col) = h;
            }
            if (row + 8 < nrows) {
                float g0 = ct[mi][ni][2], g1 = ct[mi][ni][3];
                float u0 = ct[mi][ni + 4][2], u1 = ct[mi][ni + 4][3];
                __half2 h = __floats2half2_rn(g0 / (1.f + expf(-g0)) * u0,
                                              g1 / (1.f + expf(-g1)) * u1);
                *(__half2*)(act + (size_t)(row + 8) * Ihalf + col) = h;
            }
        }
    }
}

// ---------------- gemm2 (mma.sync): C[128,128] = act[128,K] * Wd[128,K]^T -> fp32 ----------------
__global__ void __launch_bounds__(256) gemm2_mma(int shared_mode) {
    int e = blockIdx.z;
    const __half* A; const __half* B; float* C;
    int nrows, K;
    if (shared_mode) { A = g_ashh; B = g_wsdh; C = g_sout; nrows = T_TOK; K = ISH; }
    else {
        A = g_acth + (size_t)e * T_TOK * IEXP;
        B = g_w2h + (size_t)e * HID * IEXP;
        C = g_ysc + (size_t)e * T_TOK * HID;
        nrows = g_cnt[e]; K = IEXP;
    }
    int m0 = blockIdx.y * 128;
    if (m0 >= nrows) return;
    int n0 = blockIdx.x * 128;

    extern __shared__ char smraw[];
    uint32_t sb = (smem_u32(smraw) + 1023) & ~1023u;
    int tid = threadIdx.x, lane = tid & 31, wid = tid >> 5;
    int wm = wid & 3, wn = wid >> 2;

    const __half* asrc[4]; const __half* bsrc[4]; uint32_t swz[4];
#pragma unroll
    for (int i = 0; i < 4; i++) {
        int row = (tid >> 3) + 32 * i;
        int c16 = tid & 7;
        asrc[i] = A + (size_t)(m0 + row) * K + c16 * 8;
        bsrc[i] = B + (size_t)(n0 + row) * K + c16 * 8;
        swz[i] = SWZ((uint32_t)(row * 128 + c16 * 16));
    }

    const int KT = K / 64;
    for (int s = 0; s < NSTAGE - 1; s++) {
        uint32_t sA = sb + s * STAGE_B, sB = sA + 16384;
        int ko = s * 64;
#pragma unroll
        for (int i = 0; i < 4; i++) { CP16(sA + swz[i], asrc[i] + ko); CP16(sB + swz[i], bsrc[i] + ko); }
        CPCOMMIT();
    }

    float ct[2][8][4];
#pragma unroll
    for (int mi = 0; mi < 2; mi++)
#pragma unroll
        for (int j = 0; j < 8; j++)
#pragma unroll
            for (int q = 0; q < 4; q++) ct[mi][j][q] = 0.f;

    uint32_t l15 = (uint32_t)(lane & 15);
    uint32_t kcb = ((lane >> 4) << 4);

    for (int kt = 0; kt < KT; kt++) {
        CPWAIT(1);
        __syncthreads();
        uint32_t sA = sb + (kt % NSTAGE) * STAGE_B, sB = sA + 16384;
#pragma unroll
        for (int ks = 0; ks < 4; ks++) {
            uint32_t a0[4], a1[4];
            ldsm4(sA + SWZ((uint32_t)((wm * 32 + l15) * 128) + ks * 32 + kcb), a0[0], a0[1], a0[2], a0[3]);
            ldsm4(sA + SWZ((uint32_t)((wm * 32 + 16 + l15) * 128) + ks * 32 + kcb), a1[0], a1[1], a1[2], a1[3]);
#pragma unroll
            for (int bb = 0; bb < 4; bb++) {
                uint32_t b0, b1, b2, b3;
                ldsm4(sB + SWZ((uint32_t)((wn * 64 + bb * 16 + l15) * 128) + ks * 32 + kcb), b0, b1, b2, b3);
                mma16816(ct[0][2 * bb],     a0[0], a0[1], a0[2], a0[3], b0, b2);
                mma16816(ct[0][2 * bb + 1], a0[0], a0[1], a0[2], a0[3], b1, b3);
                mma16816(ct[1][2 * bb],     a1[0], a1[1], a1[2], a1[3], b0, b2);
                mma16816(ct[1][2 * bb + 1], a1[0], a1[1], a1[2], a1[3], b1, b3);
            }
        }
        __syncthreads();
        int nc = kt + NSTAGE - 1;
        if (nc < KT) {
            uint32_t dA = sb + (nc % NSTAGE) * STAGE_B, dB = dA + 16384;
            int ko = nc * 64;
#pragma unroll
            for (int i = 0; i < 4; i++) { CP16(dA + swz[i], asrc[i] + ko); CP16(dB + swz[i], bsrc[i] + ko); }
        }
        CPCOMMIT();
    }

#pragma unroll
    for (int mi = 0; mi < 2; mi++) {
        int row = m0 + wm * 32 + mi * 16 + (lane >> 2);
#pragma unroll
        for (int ni = 0; ni < 8; ni++) {
            int col = n0 + wn * 64 + ni * 8 + (lane & 3) * 2;
            if (row < nrows)
                *(float2*)(C + (size_t)row * HID + col) = make_float2(ct[mi][ni][0], ct[mi][ni][1]);
            if (row + 8 < nrows)
                *(float2*)(C + (size_t)(row + 8) * HID + col) = make_float2(ct[mi][ni][2], ct[mi][ni][3]);
        }
    }
}

// ---------------- combine ----------------
__global__ void combine_kernel(float* __restrict__ out) {
    size_t idx = (size_t)blockIdx.x * 256 + threadIdx.x;
    int t = (int)(idx >> 11);
    int h = (int)(idx & 2047);
    float v = g_sout[idx];
#pragma unroll
    for (int k = 0; k < TOPK; k++) {
        int e = g_te[t * TOPK + k];
        int s = g_slot[t * TOPK + k];
        float w = g_tw[t * TOPK + k];
        v = fmaf(w, g_ysc[((size_t)e * T_TOK + s) * HID + h], v);
    }
    out[idx] = v;
}

extern "C" void kernel_launch(void* const* d_in, const int* in_sizes, int n_in,
                              void* d_out, int out_size) {
    const float* x   = (const float*)d_in[0];
    const float* Wg  = (const float*)d_in[1];
    const float* W1  = (const float*)d_in[2];
    const float* W2  = (const float*)d_in[3];
    const float* Wsg = (const float*)d_in[4];
    const float* Wsd = (const float*)d_in[5];
    float* out = (float*)d_out;

    cudaFuncSetAttribute(gemm1_mma, cudaFuncAttributeMaxDynamicSharedMemorySize, SMEM_DYN);
    cudaFuncSetAttribute(gemm2_mma, cudaFuncAttributeMaxDynamicSharedMemorySize, SMEM_DYN);

    __half* w1h; __half* w2h; __half* wsgh; __half* wsdh; __half* xh;
    cudaGetSymbolAddress((void**)&w1h, g_w1h);
    cudaGetSymbolAddress((void**)&w2h, g_w2h);
    cudaGetSymbolAddress((void**)&wsgh, g_wsgh);
    cudaGetSymbolAddress((void**)&wsdh, g_wsdh);
    cudaGetSymbolAddress((void**)&xh, g_xh);

    // Side streams + events created once (host objects only; identical work every call).
    struct Res {
        cudaStream_t s1, s2;
        cudaEvent_t evFork, evW1, evW2, evWsd;
        Res() {
            cudaStreamCreateWithFlags(&s1, cudaStreamNonBlocking);
            cudaStreamCreateWithFlags(&s2, cudaStreamNonBlocking);
            cudaEventCreateWithFlags(&evFork, cudaEventDisableTiming);
            cudaEventCreateWithFlags(&evW1, cudaEventDisableTiming);
            cudaEventCreateWithFlags(&evW2, cudaEventDisableTiming);
            cudaEventCreateWithFlags(&evWsd, cudaEventDisableTiming);
        }
    };
    static Res r;

    // Fork side streams off the origin (stream 0).
    cudaEventRecord(r.evFork, 0);
    cudaStreamWaitEvent(r.s1, r.evFork, 0);
    cudaStreamWaitEvent(r.s2, r.evFork, 0);

    // s1: biggest conv (W1) — hidden under stream0's prologue + shared gemm1.
    conv_kernel<<<(NEXP * 2 * IEXP * HID) / 2048, 256, 0, r.s1>>>(W1, w1h);
    cudaEventRecord(r.evW1, r.s1);

    // s2: W2 and Wsd convs — hidden under expert gemm1.
    conv_kernel<<<(NEXP * HID * IEXP) / 2048, 256, 0, r.s2>>>(W2, w2h);
    cudaEventRecord(r.evW2, r.s2);
    conv_kernel<<<(HID * ISH) / 2048, 256, 0, r.s2>>>(Wsd, wsdh);
    cudaEventRecord(r.evWsd, r.s2);

    // stream 0: serialized compute chain with just-in-time waits.
    conv_kernel<<<(T_TOK * HID) / 2048, 256>>>(x, xh);
    conv_kernel<<<(2 * ISH * HID) / 2048, 256>>>(Wsg, wsgh);
    zero_kernel<<<1, 32>>>();
    router_kernel<<<T_TOK, 128>>>(x, Wg);
    gather_kernel<<<T_TOK * TOPK, 256>>>();

    gemm1_mma<<<dim3(ISH / 64, T_TOK / 128, 1), 256, SMEM_DYN>>>(1);        // shared gemm1

    cudaStreamWaitEvent(0, r.evW1, 0);
    gemm1_mma<<<dim3(IEXP / 64, T_TOK / 128, NEXP), 256, SMEM_DYN>>>(0);    // expert gemm1

    cudaStreamWaitEvent(0, r.evW2, 0);
    gemm2_mma<<<dim3(HID / 128, T_TOK / 128, NEXP), 256, SMEM_DYN>>>(0);    // expert gemm2

    cudaStreamWaitEvent(0, r.evWsd, 0);
    gemm2_mma<<<dim3(HID / 128, T_TOK / 128, 1), 256, SMEM_DYN>>>(1);       // shared gemm2

    combine_kernel<<<(T_TOK * HID) / 256, 256>>>(out);
}